// round 11
// baseline (speedup 1.0000x reference)
#include <cuda_runtime.h>

// ---------------------------------------------------------------------------
// SimpleRNN: x[128,1024,256], W_i2h[512,768] (=[Wx|Wh]), b_i2h[512],
//            W_h2o[256,512], b_h2o[256]
// out = concat( outputs[128,1024,256], h_last[128,512] ), fp32
// ---------------------------------------------------------------------------

namespace {
constexpr int B_ = 128;   // batch
constexpr int S_ = 1024;  // seq
constexpr int I_ = 256;   // in
constexpr int H_ = 512;   // hid
constexpr int O_ = 256;   // out
constexpr int BG = 8;     // batch groups
constexpr int JG = 16;    // hid groups (CTAs per batch group)
constexpr int BSL = B_ / BG;  // 16 batch rows per group
}

// Scratch (allocation-free rule: __device__ globals)
__device__ float    g_xw[(size_t)S_ * B_ * H_];   // 256 MB, [t][b][h]
__device__ float    g_hs[(size_t)S_ * B_ * H_];   // 256 MB, [t][b][h]
__device__ unsigned g_flag[BG * S_ * JG];         // per-(bg,t,jg) done flags

// ---------------------------------------------------------------------------
__global__ void zero_flag_kernel() {
    int i = blockIdx.x * blockDim.x + threadIdx.x;
    if (i < BG * S_ * JG) g_flag[i] = 0u;
}

// ---------------------------------------------------------------------------
// C[r][c] = sum_k A'[r][k]*B[c][k] + bias[c].  128x128 tile, 8x8 micro-tile
// (split halves: rows {ty*4, ty*4+64}, cols {tx*4, tx*4+64} -> conflict-free
// LDS.128 fragment reads).  Row r: hi=r/D, lo=r%D; A row = (lo*SWAP+hi)*K.
template<int K, int N, int BSTR, int D, int SWAP>
__global__ void __launch_bounds__(256, 2) gemm_bias_kernel(
    const float* __restrict__ A, const float* __restrict__ Bm,
    const float* __restrict__ bias, float* __restrict__ C)
{
    __shared__ float As[16][132];
    __shared__ float Bs[16][132];
    const int tid = threadIdx.x;
    const int r0  = blockIdx.y * 128;
    const int c0  = blockIdx.x * 128;

    // A loads: row = r0 + (tid>>1), two float4 at k = (tid&1)*8 (+0,+4)
    const int arow_l = tid >> 1;
    const int ak     = (tid & 1) * 8;
    const int r  = r0 + arow_l;
    const int hi = r / D, lo = r % D;
    const float* Arow = A + ((size_t)lo * SWAP + hi) * K + ak;

    // B loads: col = r0-like row = tid>>1, two float4 at k = (tid&1)*8
    const float* Brow = Bm + (size_t)(c0 + arow_l) * BSTR + ak;

    const int ty = tid >> 4, tx = tid & 15;
    float acc[2][4][2][4] = {};

    float4 a0 = *reinterpret_cast<const float4*>(Arow);
    float4 a1 = *reinterpret_cast<const float4*>(Arow + 4);
    float4 b0 = *reinterpret_cast<const float4*>(Brow);
    float4 b1 = *reinterpret_cast<const float4*>(Brow + 4);

    for (int kc = 0; kc < K; kc += 16) {
        __syncthreads();
        As[ak+0][arow_l]=a0.x; As[ak+1][arow_l]=a0.y; As[ak+2][arow_l]=a0.z; As[ak+3][arow_l]=a0.w;
        As[ak+4][arow_l]=a1.x; As[ak+5][arow_l]=a1.y; As[ak+6][arow_l]=a1.z; As[ak+7][arow_l]=a1.w;
        Bs[ak+0][arow_l]=b0.x; Bs[ak+1][arow_l]=b0.y; Bs[ak+2][arow_l]=b0.z; Bs[ak+3][arow_l]=b0.w;
        Bs[ak+4][arow_l]=b1.x; Bs[ak+5][arow_l]=b1.y; Bs[ak+6][arow_l]=b1.z; Bs[ak+7][arow_l]=b1.w;
        __syncthreads();
        if (kc + 16 < K) {   // register prefetch of next chunk
            a0 = *reinterpret_cast<const float4*>(Arow + kc + 16);
            a1 = *reinterpret_cast<const float4*>(Arow + kc + 16 + 4);
            b0 = *reinterpret_cast<const float4*>(Brow + kc + 16);
            b1 = *reinterpret_cast<const float4*>(Brow + kc + 16 + 4);
        }
#pragma unroll
        for (int kk = 0; kk < 16; ++kk) {
            float4 af0 = *reinterpret_cast<const float4*>(&As[kk][ty * 4]);
            float4 af1 = *reinterpret_cast<const float4*>(&As[kk][ty * 4 + 64]);
            float4 bf0 = *reinterpret_cast<const float4*>(&Bs[kk][tx * 4]);
            float4 bf1 = *reinterpret_cast<const float4*>(&Bs[kk][tx * 4 + 64]);
            float av[2][4] = {{af0.x,af0.y,af0.z,af0.w},{af1.x,af1.y,af1.z,af1.w}};
            float bv[2][4] = {{bf0.x,bf0.y,bf0.z,bf0.w},{bf1.x,bf1.y,bf1.z,bf1.w}};
#pragma unroll
            for (int ri = 0; ri < 2; ++ri)
#pragma unroll
                for (int i = 0; i < 4; ++i)
#pragma unroll
                    for (int ci = 0; ci < 2; ++ci)
#pragma unroll
                        for (int j = 0; j < 4; ++j)
                            acc[ri][i][ci][j] = fmaf(av[ri][i], bv[ci][j], acc[ri][i][ci][j]);
        }
    }

    float4 bsv0 = *reinterpret_cast<const float4*>(bias + c0 + tx * 4);
    float4 bsv1 = *reinterpret_cast<const float4*>(bias + c0 + 64 + tx * 4);
    float bb[2][4] = {{bsv0.x,bsv0.y,bsv0.z,bsv0.w},{bsv1.x,bsv1.y,bsv1.z,bsv1.w}};
#pragma unroll
    for (int ri = 0; ri < 2; ++ri)
#pragma unroll
        for (int i = 0; i < 4; ++i) {
            const size_t rowoff = (size_t)(r0 + ri * 64 + ty * 4 + i) * N;
#pragma unroll
            for (int ci = 0; ci < 2; ++ci) {
                float4 v;
                v.x = acc[ri][i][ci][0] + bb[ci][0];
                v.y = acc[ri][i][ci][1] + bb[ci][1];
                v.z = acc[ri][i][ci][2] + bb[ci][2];
                v.w = acc[ri][i][ci][3] + bb[ci][3];
                *reinterpret_cast<float4*>(C + rowoff + c0 + ci * 64 + tx * 4) = v;
            }
        }
}

// ---------------------------------------------------------------------------
// Multi-value butterfly: merge HALF*2 accs across lanes at xor-offset O.
#define RED_LEVEL(O, HALF)                                                   \
    {                                                                        \
        const bool up_ = (lane & (O)) != 0;                                  \
        _Pragma("unroll")                                                    \
        for (int q_ = 0; q_ < (HALF); ++q_) {                                \
            float s_ = up_ ? A[q_] : A[q_ + (HALF)];                         \
            float r_ = __shfl_xor_sync(0xffffffffu, s_, (O));                \
            A[q_] = (up_ ? A[q_ + (HALF)] : A[q_]) + r_;                     \
        }                                                                    \
    }

// Persistent scan. Grid (JG, BG) = (16, 8), 256 threads.
// CTA (jg,bg): hid slice [jg*32, +32), batch slice [bg*16, +16).
// Lane owns k-slice {4*lane + 128*i + c : i=0..3, c=0..3} (float4-friendly).
// Each lane carries all 64 accs (16 b x 4 j); one 62-shuffle merge leaves
// 2 finished outputs per lane.  h_{t-1} staged in 2 pipelined 16KB chunks.
__global__ void __launch_bounds__(256, 1) rnn_scan_kernel(const float* __restrict__ W)
{
    const int jg    = blockIdx.x;   // 0..15
    const int bg    = blockIdx.y;   // 0..7
    const int tid   = threadIdx.x;
    const int warp  = tid >> 5;
    const int lane  = tid & 31;
    const int jbase = jg * 32 + warp * 4;

    __shared__ float hbuf[2][BSL * 256];   // 2 x 16KB k-chunks of h_{t-1}

    // Register-resident Wh slice: w4[jj][i] = Wh[jbase+jj][128*i + 4*lane ..+3]
    float4 w4[4][4];
#pragma unroll
    for (int jj = 0; jj < 4; ++jj)
#pragma unroll
        for (int i = 0; i < 4; ++i)
            w4[jj][i] = *reinterpret_cast<const float4*>(
                W + (size_t)(jbase + jj) * (I_ + H_) + I_ + 128 * i + 4 * lane);

    unsigned* flg = g_flag + (size_t)bg * S_ * JG;
    const int ob = lane >> 1;                 // batch this lane finalizes
    const int oj = jbase + (lane & 1) * 2;    // first of 2 consecutive j's
    const int sb = tid >> 6;                  // staging: b-subrow  (4 f4/chunk)
    const int sc = (tid & 63) * 4;            // staging: k offset within chunk

    for (int t = 0; t < S_; ++t) {
        float s0 = 0.f, s1 = 0.f;
        const size_t rowoff = ((size_t)t * B_ + bg * BSL + ob) * H_ + oj;

        if (t > 0) {
            // acquire: parallel poll of the 16 per-jg flags for step t-1
            if (warp == 0) {
                const unsigned* f = flg + (size_t)(t - 1) * JG + (lane & 15);
                unsigned v;
                do {
                    asm volatile("ld.relaxed.gpu.global.u32 %0, [%1];"
                                 : "=r"(v) : "l"(f) : "memory");
                } while (!__all_sync(0xffffffffu, v != 0u));
                asm volatile("fence.acq_rel.gpu;" ::: "memory");
            }
            __syncthreads();

            float2 xv = *reinterpret_cast<const float2*>(g_xw + rowoff); // early
            const float* rowbase = g_hs + ((size_t)(t - 1) * B_ + bg * BSL) * H_;

            float A[64];   // A[b*4+jj]
#pragma unroll
            for (int q = 0; q < 64; ++q) A[q] = 0.f;

            // prefetch chunk 0 (k in [0,256)): 4 float4 / thread
            float4 p0, p1, p2, p3;
            {
                const float* src = rowbase + sb * H_ + sc;
                p0 = *reinterpret_cast<const float4*>(src);
                p1 = *reinterpret_cast<const float4*>(src + 4 * H_);
                p2 = *reinterpret_cast<const float4*>(src + 8 * H_);
                p3 = *reinterpret_cast<const float4*>(src + 12 * H_);
            }
#pragma unroll
            for (int c = 0; c < 2; ++c) {
                float* hb = hbuf[c];
                *reinterpret_cast<float4*>(hb + (sb +  0) * 256 + sc) = p0;
                *reinterpret_cast<float4*>(hb + (sb +  4) * 256 + sc) = p1;
                *reinterpret_cast<float4*>(hb + (sb +  8) * 256 + sc) = p2;
                *reinterpret_cast<float4*>(hb + (sb + 12) * 256 + sc) = p3;
                if (c == 0) {   // prefetch chunk 1 (k in [256,512))
                    const float* src = rowbase + sb * H_ + 256 + sc;
                    p0 = *reinterpret_cast<const float4*>(src);
                    p1 = *reinterpret_cast<const float4*>(src + 4 * H_);
                    p2 = *reinterpret_cast<const float4*>(src + 8 * H_);
                    p3 = *reinterpret_cast<const float4*>(src + 12 * H_);
                }
                __syncthreads();
#pragma unroll
                for (int i2 = 0; i2 < 2; ++i2) {
                    const int i = c * 2 + i2;
#pragma unroll
                    for (int b = 0; b < 16; ++b) {
                        float4 hv = *reinterpret_cast<const float4*>(
                            hb + b * 256 + i2 * 128 + 4 * lane);
#pragma unroll
                        for (int jj = 0; jj < 4; ++jj) {
                            float a = A[b * 4 + jj];
                            a = fmaf(hv.x, w4[jj][i].x, a);
                            a = fmaf(hv.y, w4[jj][i].y, a);
                            a = fmaf(hv.z, w4[jj][i].z, a);
                            a = fmaf(hv.w, w4[jj][i].w, a);
                            A[b * 4 + jj] = a;
                        }
                    }
                }
                if (c == 0) __syncthreads();   // before overwriting is not
                                               // needed (2 bufs), but protects
                                               // chunk-1 STS vs chunk-0 reads
            }
            RED_LEVEL(16, 32)
            RED_LEVEL(8, 16)
            RED_LEVEL(4, 8)
            RED_LEVEL(2, 4)
            RED_LEVEL(1, 2)
            s0 = A[0];
            s1 = A[1];

            float2 hv2;
            hv2.x = tanhf(xv.x + s0);
            hv2.y = tanhf(xv.y + s1);
            *reinterpret_cast<float2*>(g_hs + rowoff) = hv2;
        } else {
            float2 xv = *reinterpret_cast<const float2*>(g_xw + rowoff);
            float2 hv2;
            hv2.x = tanhf(xv.x);
            hv2.y = tanhf(xv.y);
            *reinterpret_cast<float2*>(g_hs + rowoff) = hv2;
        }

        __syncthreads();
        if (tid == 0) {   // release: publish our hid slice of h_t
            asm volatile("fence.acq_rel.gpu;" ::: "memory");
            asm volatile("st.relaxed.gpu.global.u32 [%0], %1;"
                         :: "l"(flg + (size_t)t * JG + jg), "r"(1u) : "memory");
        }
    }
}

// ---------------------------------------------------------------------------
__global__ void copy_hlast_kernel(float* __restrict__ out) {
    int i = blockIdx.x * blockDim.x + threadIdx.x;
    out[i] = g_hs[(size_t)(S_ - 1) * B_ * H_ + i];   // [b][h] slice, contiguous
}

// ---------------------------------------------------------------------------
extern "C" void kernel_launch(void* const* d_in, const int* in_sizes, int n_in,
                              void* d_out, int out_size)
{
    const float* x  = (const float*)d_in[0];   // [128,1024,256]
    const float* Wi = (const float*)d_in[1];   // [512,768]
    const float* bi = (const float*)d_in[2];   // [512]
    const float* Wo = (const float*)d_in[3];   // [256,512]
    const float* bo = (const float*)d_in[4];   // [256]
    float* out = (float*)d_out;

    float* xw_d = nullptr;
    float* hs_d = nullptr;
    cudaGetSymbolAddress((void**)&xw_d, g_xw);
    cudaGetSymbolAddress((void**)&hs_d, g_hs);

    // reset sync flags (graph replays must be deterministic)
    zero_flag_kernel<<<(BG * S_ * JG + 255) / 256, 256>>>();

    // Phase 1: xW[t][b][h]  (r = t*128+b, A row = (b*S_+t)*I_)
    {
        dim3 g(H_ / 128, (S_ * B_) / 128);
        gemm_bias_kernel<I_, H_, I_ + H_, B_, S_><<<g, 256>>>(x, Wi, bi, xw_d);
    }

    // Phase 2: sequential scan (persistent, 128 co-resident CTAs)
    rnn_scan_kernel<<<dim3(JG, BG), 256>>>(Wi);

    // Phase 3: outputs[b][s][o]  (r = b*S_+s, A row = (s*B_+b)*H_)
    {
        dim3 g(O_ / 128, (B_ * S_) / 128);
        gemm_bias_kernel<H_, O_, H_, S_, B_><<<g, 256>>>(hs_d, Wo, bo, out);
    }

    // h_last
    if (out_size >= B_ * S_ * O_ + B_ * H_)
        copy_hlast_kernel<<<(B_ * H_) / 256, 256>>>(out + (size_t)B_ * S_ * O_);
}

// round 13
// speedup vs baseline: 1.5042x; 1.5042x over previous
#include <cuda_runtime.h>

// ---------------------------------------------------------------------------
// SimpleRNN: x[128,1024,256], W_i2h[512,768] (=[Wx|Wh]), b_i2h[512],
//            W_h2o[256,512], b_h2o[256]
// out = concat( outputs[128,1024,256], h_last[128,512] ), fp32
// ---------------------------------------------------------------------------

namespace {
constexpr int B_ = 128;   // batch
constexpr int S_ = 1024;  // seq
constexpr int I_ = 256;   // in
constexpr int H_ = 512;   // hid
constexpr int O_ = 256;   // out
constexpr int BG = 8;     // batch groups
constexpr int JG = 16;    // hid groups (CTAs per batch group)
constexpr int BSL = B_ / BG;  // 16 batch rows per group
}

// Scratch (allocation-free rule: __device__ globals)
__device__ float    g_xw[(size_t)S_ * B_ * H_];   // 256 MB, [t][b][h]
__device__ float    g_hs[(size_t)S_ * B_ * H_];   // 256 MB, [t][b][h]
__device__ unsigned g_flag[BG * S_ * JG];         // per-(bg,t,jg) done flags

// ---------------------------------------------------------------------------
__global__ void zero_flag_kernel() {
    int i = blockIdx.x * blockDim.x + threadIdx.x;
    if (i < BG * S_ * JG) g_flag[i] = 0u;
}

// ---------------------------------------------------------------------------
// C[r][c] = sum_k A'[r][k]*B[c][k] + bias[c].  128x128 tile, 8x8 micro-tile
// (split halves -> conflict-free LDS.128).  Row r: hi=r/D, lo=r%D;
// A row = (lo*SWAP + hi)*K.   [unchanged from round 11 — verified faster]
template<int K, int N, int BSTR, int D, int SWAP>
__global__ void __launch_bounds__(256, 2) gemm_bias_kernel(
    const float* __restrict__ A, const float* __restrict__ Bm,
    const float* __restrict__ bias, float* __restrict__ C)
{
    __shared__ float As[16][132];
    __shared__ float Bs[16][132];
    const int tid = threadIdx.x;
    const int r0  = blockIdx.y * 128;
    const int c0  = blockIdx.x * 128;

    const int arow_l = tid >> 1;
    const int ak     = (tid & 1) * 8;
    const int r  = r0 + arow_l;
    const int hi = r / D, lo = r % D;
    const float* Arow = A + ((size_t)lo * SWAP + hi) * K + ak;
    const float* Brow = Bm + (size_t)(c0 + arow_l) * BSTR + ak;

    const int ty = tid >> 4, tx = tid & 15;
    float acc[2][4][2][4] = {};

    float4 a0 = *reinterpret_cast<const float4*>(Arow);
    float4 a1 = *reinterpret_cast<const float4*>(Arow + 4);
    float4 b0 = *reinterpret_cast<const float4*>(Brow);
    float4 b1 = *reinterpret_cast<const float4*>(Brow + 4);

    for (int kc = 0; kc < K; kc += 16) {
        __syncthreads();
        As[ak+0][arow_l]=a0.x; As[ak+1][arow_l]=a0.y; As[ak+2][arow_l]=a0.z; As[ak+3][arow_l]=a0.w;
        As[ak+4][arow_l]=a1.x; As[ak+5][arow_l]=a1.y; As[ak+6][arow_l]=a1.z; As[ak+7][arow_l]=a1.w;
        Bs[ak+0][arow_l]=b0.x; Bs[ak+1][arow_l]=b0.y; Bs[ak+2][arow_l]=b0.z; Bs[ak+3][arow_l]=b0.w;
        Bs[ak+4][arow_l]=b1.x; Bs[ak+5][arow_l]=b1.y; Bs[ak+6][arow_l]=b1.z; Bs[ak+7][arow_l]=b1.w;
        __syncthreads();
        if (kc + 16 < K) {
            a0 = *reinterpret_cast<const float4*>(Arow + kc + 16);
            a1 = *reinterpret_cast<const float4*>(Arow + kc + 16 + 4);
            b0 = *reinterpret_cast<const float4*>(Brow + kc + 16);
            b1 = *reinterpret_cast<const float4*>(Brow + kc + 16 + 4);
        }
#pragma unroll
        for (int kk = 0; kk < 16; ++kk) {
            float4 af0 = *reinterpret_cast<const float4*>(&As[kk][ty * 4]);
            float4 af1 = *reinterpret_cast<const float4*>(&As[kk][ty * 4 + 64]);
            float4 bf0 = *reinterpret_cast<const float4*>(&Bs[kk][tx * 4]);
            float4 bf1 = *reinterpret_cast<const float4*>(&Bs[kk][tx * 4 + 64]);
            float av[2][4] = {{af0.x,af0.y,af0.z,af0.w},{af1.x,af1.y,af1.z,af1.w}};
            float bv[2][4] = {{bf0.x,bf0.y,bf0.z,bf0.w},{bf1.x,bf1.y,bf1.z,bf1.w}};
#pragma unroll
            for (int ri = 0; ri < 2; ++ri)
#pragma unroll
                for (int i = 0; i < 4; ++i)
#pragma unroll
                    for (int ci = 0; ci < 2; ++ci)
#pragma unroll
                        for (int j = 0; j < 4; ++j)
                            acc[ri][i][ci][j] = fmaf(av[ri][i], bv[ci][j], acc[ri][i][ci][j]);
        }
    }

    float4 bsv0 = *reinterpret_cast<const float4*>(bias + c0 + tx * 4);
    float4 bsv1 = *reinterpret_cast<const float4*>(bias + c0 + 64 + tx * 4);
    float bb[2][4] = {{bsv0.x,bsv0.y,bsv0.z,bsv0.w},{bsv1.x,bsv1.y,bsv1.z,bsv1.w}};
#pragma unroll
    for (int ri = 0; ri < 2; ++ri)
#pragma unroll
        for (int i = 0; i < 4; ++i) {
            const size_t rowoff = (size_t)(r0 + ri * 64 + ty * 4 + i) * N;
#pragma unroll
            for (int ci = 0; ci < 2; ++ci) {
                float4 v;
                v.x = acc[ri][i][ci][0] + bb[ci][0];
                v.y = acc[ri][i][ci][1] + bb[ci][1];
                v.z = acc[ri][i][ci][2] + bb[ci][2];
                v.w = acc[ri][i][ci][3] + bb[ci][3];
                *reinterpret_cast<float4*>(C + rowoff + c0 + ci * 64 + tx * 4) = v;
            }
        }
}

// ---------------------------------------------------------------------------
// Multi-value butterfly: merge HALF*2 accs across lanes at xor-offset O.
#define RED_LEVEL(O, HALF)                                                   \
    {                                                                        \
        const bool up_ = (lane & (O)) != 0;                                  \
        _Pragma("unroll")                                                    \
        for (int q_ = 0; q_ < (HALF); ++q_) {                                \
            float s_ = up_ ? A[q_] : A[q_ + (HALF)];                         \
            float r_ = __shfl_xor_sync(0xffffffffu, s_, (O));                \
            A[q_] = (up_ ? A[q_ + (HALF)] : A[q_]) + r_;                     \
        }                                                                    \
    }

// Persistent scan. Grid (JG, BG) = (16, 8), 256 threads.
// CTA (jg,bg): hid slice [jg*32, +32), batch slice [bg*16, +16).
// Round-10 structure (single staged buffer, two barriers) + float4 LDS:
// lane owns k-slice {4*lane + 128*i + c}.  Each lane carries all 64 accs
// (16 b x 4 j); one 62-shuffle merge leaves 2 finished outputs per lane.
__global__ void __launch_bounds__(256, 1) rnn_scan_kernel(const float* __restrict__ W)
{
    const int jg    = blockIdx.x;   // 0..15
    const int bg    = blockIdx.y;   // 0..7
    const int tid   = threadIdx.x;
    const int warp  = tid >> 5;
    const int lane  = tid & 31;
    const int jbase = jg * 32 + warp * 4;

    __shared__ float hsm[BSL * H_];   // 32 KB: h_{t-1} for this batch group

    // Register-resident Wh slice: w4[jj][i] = Wh[jbase+jj][128*i + 4*lane ..+3]
    float4 w4[4][4];
#pragma unroll
    for (int jj = 0; jj < 4; ++jj)
#pragma unroll
        for (int i = 0; i < 4; ++i)
            w4[jj][i] = *reinterpret_cast<const float4*>(
                W + (size_t)(jbase + jj) * (I_ + H_) + I_ + 128 * i + 4 * lane);

    unsigned* flg = g_flag + (size_t)bg * S_ * JG;
    const int ob = lane >> 1;                 // batch this lane finalizes
    const int oj = jbase + (lane & 1) * 2;    // first of 2 consecutive j's

    for (int t = 0; t < S_; ++t) {
        float s0 = 0.f, s1 = 0.f;
        const size_t rowoff = ((size_t)t * B_ + bg * BSL + ob) * H_ + oj;
        float2 xv;

        if (t > 0) {
            // acquire: parallel poll of the 16 per-jg flags for step t-1
            if (warp == 0) {
                const unsigned* f = flg + (size_t)(t - 1) * JG + (lane & 15);
                unsigned v;
                do {
                    asm volatile("ld.relaxed.gpu.global.u32 %0, [%1];"
                                 : "=r"(v) : "l"(f) : "memory");
                } while (!__all_sync(0xffffffffu, v != 0u));
                asm volatile("fence.acq_rel.gpu;" ::: "memory");
            }
            __syncthreads();

            xv = *reinterpret_cast<const float2*>(g_xw + rowoff);  // early LDG
            {   // stage h_{t-1} (32 KB, 8 float4/thread, coalesced)
                const float4* src = reinterpret_cast<const float4*>(
                    g_hs + ((size_t)(t - 1) * B_ + bg * BSL) * H_);
                float4* dst = reinterpret_cast<float4*>(hsm);
#pragma unroll
                for (int i = 0; i < (BSL * H_ / 4) / 256; ++i)
                    dst[tid + 256 * i] = src[tid + 256 * i];
            }
            __syncthreads();

            float A[64];   // A[b*4+jj]
#pragma unroll
            for (int q = 0; q < 64; ++q) A[q] = 0.f;
#pragma unroll
            for (int i = 0; i < 4; ++i) {
                const int kofs = 4 * lane + 128 * i;
#pragma unroll
                for (int b = 0; b < 16; ++b) {
                    float4 hv = *reinterpret_cast<const float4*>(hsm + b * H_ + kofs);
#pragma unroll
                    for (int jj = 0; jj < 4; ++jj) {
                        float a = A[b * 4 + jj];
                        a = fmaf(hv.x, w4[jj][i].x, a);
                        a = fmaf(hv.y, w4[jj][i].y, a);
                        a = fmaf(hv.z, w4[jj][i].z, a);
                        a = fmaf(hv.w, w4[jj][i].w, a);
                        A[b * 4 + jj] = a;
                    }
                }
            }
            RED_LEVEL(16, 32)
            RED_LEVEL(8, 16)
            RED_LEVEL(4, 8)
            RED_LEVEL(2, 4)
            RED_LEVEL(1, 2)
            s0 = A[0];
            s1 = A[1];
        } else {
            xv = *reinterpret_cast<const float2*>(g_xw + rowoff);
        }

        float2 hv2;
        hv2.x = tanhf(xv.x + s0);
        hv2.y = tanhf(xv.y + s1);
        *reinterpret_cast<float2*>(g_hs + rowoff) = hv2;

        __syncthreads();
        if (tid == 0) {   // release: publish our hid slice of h_t
            asm volatile("fence.acq_rel.gpu;" ::: "memory");
            asm volatile("st.relaxed.gpu.global.u32 [%0], %1;"
                         :: "l"(flg + (size_t)t * JG + jg), "r"(1u) : "memory");
        }
    }
}

// ---------------------------------------------------------------------------
__global__ void copy_hlast_kernel(float* __restrict__ out) {
    int i = blockIdx.x * blockDim.x + threadIdx.x;
    out[i] = g_hs[(size_t)(S_ - 1) * B_ * H_ + i];   // [b][h] slice, contiguous
}

// ---------------------------------------------------------------------------
extern "C" void kernel_launch(void* const* d_in, const int* in_sizes, int n_in,
                              void* d_out, int out_size)
{
    const float* x  = (const float*)d_in[0];   // [128,1024,256]
    const float* Wi = (const float*)d_in[1];   // [512,768]
    const float* bi = (const float*)d_in[2];   // [512]
    const float* Wo = (const float*)d_in[3];   // [256,512]
    const float* bo = (const float*)d_in[4];   // [256]
    float* out = (float*)d_out;

    float* xw_d = nullptr;
    float* hs_d = nullptr;
    cudaGetSymbolAddress((void**)&xw_d, g_xw);
    cudaGetSymbolAddress((void**)&hs_d, g_hs);

    // reset sync flags (graph replays must be deterministic)
    zero_flag_kernel<<<(BG * S_ * JG + 255) / 256, 256>>>();

    // Phase 1: xW[t][b][h]  (r = t*128+b, A row = (b*S_+t)*I_)
    {
        dim3 g(H_ / 128, (S_ * B_) / 128);
        gemm_bias_kernel<I_, H_, I_ + H_, B_, S_><<<g, 256>>>(x, Wi, bi, xw_d);
    }

    // Phase 2: sequential scan (persistent, 128 co-resident CTAs)
    rnn_scan_kernel<<<dim3(JG, BG), 256>>>(Wi);

    // Phase 3: outputs[b][s][o]  (r = b*S_+s, A row = (s*B_+b)*H_)
    {
        dim3 g(O_ / 128, (B_ * S_) / 128);
        gemm_bias_kernel<H_, O_, H_, S_, B_><<<g, 256>>>(hs_d, Wo, bo, out);
    }

    // h_last
    if (out_size >= B_ * S_ * O_ + B_ * H_)
        copy_hlast_kernel<<<(B_ * H_) / 256, 256>>>(out + (size_t)B_ * S_ * O_);
}